// round 14
// baseline (speedup 1.0000x reference)
#include <cuda_runtime.h>
#include <cuda_fp16.h>
#include <cstdint>

__device__ __forceinline__ float leaky(float v){ return v > 0.f ? v : 0.01f*v; }
__device__ __forceinline__ uint32_t smem_u32(const void* p){
    uint32_t a; asm("{ .reg .u64 t; cvta.to.shared.u64 t, %1; cvt.u32.u64 %0, t; }" : "=r"(a) : "l"(p));
    return a;
}
__device__ __forceinline__ void cpa16(uint32_t dst, const void* src, uint32_t sz){
    asm volatile("cp.async.cg.shared.global [%0], [%1], 16, %2;"
                 :: "r"(dst), "l"(src), "r"(sz) : "memory");
}
#define CP_COMMIT() asm volatile("cp.async.commit_group;" ::: "memory")
#define CP_WAIT0()  asm volatile("cp.async.wait_group 0;" ::: "memory")

__device__ __forceinline__ void mma16(float* c, const uint32_t* a, uint32_t b0, uint32_t b1){
    asm volatile("mma.sync.aligned.m16n8k16.row.col.f32.f16.f16.f32 "
        "{%0,%1,%2,%3}, {%4,%5,%6,%7}, {%8,%9}, {%0,%1,%2,%3};"
        : "+f"(c[0]), "+f"(c[1]), "+f"(c[2]), "+f"(c[3])
        : "r"(a[0]), "r"(a[1]), "r"(a[2]), "r"(a[3]), "r"(b0), "r"(b1));
}
__device__ __forceinline__ void ldmA(uint32_t* a, uint32_t addr){
    asm volatile("ldmatrix.sync.aligned.m8n8.x4.shared.b16 {%0,%1,%2,%3}, [%4];"
        : "=r"(a[0]), "=r"(a[1]), "=r"(a[2]), "=r"(a[3]) : "r"(addr));
}

// ---------------- device scratch ----------------
__device__ __align__(16) __half g_xcl[(size_t)2*96*96*96*32];   // x channels-last fp16
__device__ __align__(16) __half g_h  [(size_t)2*94*94*94*64];   // h channels-last fp16
__device__ __align__(16) __half g_wc1[2*27*2048];               // B fragments per 32-K chunk
__device__ __align__(16) __half g_wc2[2*54*2048];
__device__ __align__(16) __half g_wsk[2*2048];

// ---------------- prep: style MLP + modulate/demod + fp16 B-fragment tiles ----------------
__global__ void prep_kernel(const float* __restrict__ s,
                            const float* __restrict__ w1, const float* __restrict__ b1,
                            const float* __restrict__ w2, const float* __restrict__ b2,
                            const float* __restrict__ w3, const float* __restrict__ b3,
                            const float* __restrict__ wc, __half* __restrict__ gw,
                            int H1, int H2, int IC, int KD)
{
    const int n = blockIdx.x, tid = threadIdx.x;
    __shared__ float sv[64], a1[128], a2[128], mod[64], dem[64];
    if (tid < 64) sv[tid] = s[n*64 + tid];
    __syncthreads();
    if (tid < H1){
        float a = b1[tid];
        for (int k = 0; k < 64; k++) a += sv[k]*w1[tid*64 + k];
        a1[tid] = leaky(a);
    }
    __syncthreads();
    if (tid < H2){
        float a = b2[tid];
        for (int k = 0; k < H1; k++) a += a1[k]*w2[tid*H1 + k];
        a2[tid] = leaky(a);
    }
    __syncthreads();
    if (tid < IC){
        float a = b3[tid];
        for (int k = 0; k < H2; k++) a += a2[k]*w3[tid*H2 + k];
        mod[tid] = a;
    }
    __syncthreads();
    if (tid < 64){
        float ss = 0.f;
        for (int i = 0; i < IC; i++){
            float m = mod[i];
            const float* wp = wc + (tid*IC + i)*KD;
            for (int k = 0; k < KD; k++){ float t = wp[k]*m; ss += t*t; }
        }
        dem[tid] = rsqrtf(ss + 1e-8f);
    }
    __syncthreads();
    const int nsub = IC >> 5;
    const int total = KD * nsub * 2048;
    for (int e = tid; e < total; e += blockDim.x){
        int j    = e & 7;
        int lane = (e >> 3) & 31;
        int nt   = (e >> 8) & 7;
        int c    = e >> 11;
        int g    = lane >> 2, t = lane & 3;
        int oc   = nt*8 + g;
        int kloc = (j >> 2)*16 + 2*t + (j & 1) + 8*((j >> 1) & 1);
        int tap  = c / nsub, ih = c % nsub;
        int ic   = ih*32 + kloc;
        gw[(size_t)n*total + e] = __float2half_rn(wc[(oc*IC + ic)*KD + tap] * mod[ic] * dem[oc]);
    }
}

// ---------------- x -> channels-last fp16 ----------------
__global__ void xconvert_kernel(const float* __restrict__ x, __half* __restrict__ xcl)
{
    const int y = blockIdx.x, z = blockIdx.y, n = blockIdx.z;
    __shared__ float sm[32*97];
    const float* src = x + (size_t)n*28311552 + (size_t)z*9216 + (size_t)y*96;
    for (int e = threadIdx.x; e < 32*96; e += 128){
        int ic = e / 96, xx = e % 96;
        sm[ic*97 + xx] = src[(size_t)ic*884736 + xx];
    }
    __syncthreads();
    __half* dst = xcl + (size_t)n*28311552 + ((size_t)z*96 + y)*96*32;
    for (int e = threadIdx.x; e < 32*96/2; e += 128){
        int xx = e >> 4, icp = (e & 15)*2;
        __half2 v = __floats2half2_rn(sm[icp*97 + xx], sm[(icp+1)*97 + xx]);
        *(__half2*)(dst + (size_t)xx*32 + icp) = v;
    }
}

// ---------------- implicit-GEMM conv: A-resident halo, warp-staggered K-order ----------------
// CTA: 128 threads / 4 warps; tile M=256 voxels (4z x 4y x 16x) x N=64 oc.
// Full halo loaded once; warps traverse the K-chunk ring starting at offsets
// wid*NCH/4 so their load/addr phases decorrelate and the HMMA pipe stays fed.
// Per chunk: ldmA x8, B-prefetch LDGs in the LDSM shadow, two MMA blocks.
template<int IND, int OUTD, int INCH, int NCH, bool SKIP>
__global__ __launch_bounds__(128, 2)
void conv_mma(const __half* __restrict__ in,
              const __half* __restrict__ wtil,
              const __half* __restrict__ wskip,
              const __half* __restrict__ xclp,
              const float* __restrict__ bias1,
              const float* __restrict__ bias2,
              void* __restrict__ outp)
{
    constexpr int NSUB = INCH >> 5;
    constexpr int ZT   = (OUTD + 3) / 4;
    constexpr int CHB  = INCH * 2;
    constexpr int P    = CHB / 16;
    constexpr int HALO = 648 * CHB;
    constexpr int SKT  = SKIP ? 16384 : 0;
    constexpr int BIAS = HALO + SKT;
    constexpr int TOT  = 648 * P;

    extern __shared__ __align__(16) unsigned char smem[];
    const uint32_t sb = smem_u32(smem);
    float* sbias = (float*)(smem + BIAS);

    const int tid  = threadIdx.x;
    const int lane = tid & 31;
    const int wid  = tid >> 5;
    const int g    = lane >> 2;
    const int t    = lane & 3;
    const int strip = wid * 64;

    const int bx = blockIdx.x, by = blockIdx.y;
    const int n  = blockIdx.z / ZT;
    const int zt = blockIdx.z % ZT;
    const int z0 = zt*4, y0 = by*4, x0 = bx*16;

    const __half* inb = in + (size_t)n*IND*IND*IND*INCH;
    const __half* xb  = SKIP ? (xclp + (size_t)n*28311552) : nullptr;
    const __half* wb  = wtil + (size_t)n*(NCH - (SKIP?1:0))*2048;
    const __half* wsb = SKIP ? (wskip + (size_t)n*2048) : nullptr;

    if (tid < 64){
        float b = bias1[tid];
        if constexpr (SKIP) b += bias2[tid];
        sbias[tid] = b;
    }

    // ---- one-time full halo load (slot-swizzled channels-last) ----
    #pragma unroll 4
    for (int e = tid; e < TOT; e += 128){
        int vox = e / P, j = e % P;
        int hx = vox % 18, hy = (vox/18) % 6, hz = vox/108;
        bool v = (z0+hz < IND) && (y0+hy < IND) && (x0+hx < IND);
        int key = (INCH == 64) ? (hx & 7) : ((hx >> 1) & 3);
        uint32_t dst = sb + (uint32_t)(vox*CHB + ((j ^ key) << 4));
        const __half* src = inb + (((size_t)(z0+hz)*IND + (y0+hy))*IND + (x0+hx))*INCH + j*8;
        cpa16(dst, src, v ? 16u : 0u);
    }
    if constexpr (SKIP){
        #pragma unroll 2
        for (int e = tid; e < 1024; e += 128){
            int vox = e >> 2, j = e & 3;
            int dx = vox & 15, dy = (vox >> 4) & 3, dz = vox >> 6;
            bool v = (z0+2+dz < 96) && (y0+2+dy < 96) && (x0+2+dx < 96);
            int key = (dx >> 1) & 3;
            uint32_t dst = sb + (uint32_t)(HALO + vox*64 + ((j ^ key) << 4));
            const __half* src = xb + (((size_t)(z0+2+dz)*96 + (y0+2+dy))*96 + (x0+2+dx))*32 + j*8;
            cpa16(dst, src, v ? 16u : 0u);
        }
    }
    CP_COMMIT();
    CP_WAIT0();
    __syncthreads();          // the ONLY barrier

    const int r  = ((lane >> 3) & 1)*8 + (lane & 7);
    const int kh = (lane >> 4) & 1;

    float acc[4][8][4];
    #pragma unroll
    for (int mt = 0; mt < 4; mt++)
        #pragma unroll
        for (int nt = 0; nt < 8; nt++)
            #pragma unroll
            for (int q = 0; q < 4; q++) acc[mt][nt][q] = 0.f;

    auto bptr = [&](int kc) -> const uint4* {
        const __half* bs = (SKIP && kc == NCH-1) ? wsb : (wb + (size_t)kc*2048);
        return (const uint4*)bs + lane;
    };

    // warp-staggered start offset in the chunk ring
    const int kc0 = (wid * NCH) >> 2;

    uint4 bcur[8];
    {
        const uint4* p = bptr(kc0);
        #pragma unroll
        for (int nt = 0; nt < 8; nt++) bcur[nt] = __ldg(p + nt*32);
    }

    #pragma unroll 1
    for (int i = 0; i < NCH; i++){
        int kc = kc0 + i; if (kc >= NCH) kc -= NCH;

        // A addresses for this chunk (per-chunk; NSUB shift is compile-time)
        uint32_t a[2][4][4];
        if (SKIP && kc == NCH - 1){
            #pragma unroll
            for (int mt = 0; mt < 4; mt++){
                int m = strip + mt*16 + r;
                int key2 = ((m & 15) >> 1) & 3;
                uint32_t b2 = sb + (uint32_t)(HALO + m*64);
                #pragma unroll
                for (int s = 0; s < 2; s++){
                    int slot = 2*s + kh;
                    ldmA(a[s][mt], b2 + (uint32_t)((slot ^ key2) << 4));
                }
            }
        } else {
            const int tap = kc / NSUB;
            const int ih  = kc - tap*NSUB;
            const int kz = tap/9, rem = tap - 9*kz;
            const int ky = rem/3, kx = rem - 3*ky;
            const int slotbase = ih*4;
            #pragma unroll
            for (int mt = 0; mt < 4; mt++){
                int m = strip + mt*16 + r;
                int hz = (m >> 6) + kz, hy = ((m >> 4) & 3) + ky, hx = (m & 15) + kx;
                int hi = (hz*6 + hy)*18 + hx;
                int key = (INCH == 64) ? (hx & 7) : ((hx >> 1) & 3);
                uint32_t base = sb + (uint32_t)(hi*CHB);
                #pragma unroll
                for (int s = 0; s < 2; s++){
                    int slot = slotbase + 2*s + kh;
                    ldmA(a[s][mt], base + (uint32_t)((slot ^ key) << 4));
                }
            }
        }

        // B prefetch for next chunk in the LDSM shadow
        uint4 bnxt[8];
        const bool pf = (i + 1 < NCH);
        if (pf){
            int kn = kc + 1; if (kn >= NCH) kn = 0;
            const uint4* p = bptr(kn);
            #pragma unroll
            for (int nt = 0; nt < 8; nt++) bnxt[nt] = __ldg(p + nt*32);
        }

        #pragma unroll
        for (int nt = 0; nt < 8; nt++)
            #pragma unroll
            for (int mt = 0; mt < 4; mt++)
                mma16(acc[mt][nt], a[0][mt], bcur[nt].x, bcur[nt].y);

        #pragma unroll
        for (int nt = 0; nt < 8; nt++)
            #pragma unroll
            for (int mt = 0; mt < 4; mt++)
                mma16(acc[mt][nt], a[1][mt], bcur[nt].z, bcur[nt].w);

        if (pf){
            #pragma unroll
            for (int nt = 0; nt < 8; nt++) bcur[nt] = bnxt[nt];
        }
    }

    // ---------------- epilogue ----------------
    #pragma unroll
    for (int mt = 0; mt < 4; mt++){
        #pragma unroll
        for (int half = 0; half < 2; half++){
            const int row = strip + mt*16 + g + 8*half;
            const int vz = z0 + (row >> 6);
            const int vy = y0 + ((row >> 4) & 3);
            const int vx = x0 + (row & 15);
            if (vz >= OUTD || vy >= OUTD || vx >= OUTD) continue;
            if constexpr (!SKIP){
                __half* dst = (__half*)outp + (((size_t)n*OUTD*OUTD*OUTD)
                            + (((size_t)vz*OUTD + vy)*OUTD + vx))*64;
                #pragma unroll
                for (int nt = 0; nt < 8; nt++){
                    const int c0 = nt*8 + 2*t;
                    float v0 = leaky(acc[mt][nt][2*half + 0] + sbias[c0]);
                    float v1 = leaky(acc[mt][nt][2*half + 1] + sbias[c0 + 1]);
                    *(__half2*)(dst + c0) = __floats2half2_rn(v0, v1);
                }
            } else {
                const size_t plane = (size_t)OUTD*OUTD*OUTD;
                float* base2 = (float*)outp + (size_t)n*64*plane
                             + (((size_t)vz*OUTD + vy)*OUTD + vx);
                #pragma unroll
                for (int nt = 0; nt < 8; nt++){
                    const int c0 = nt*8 + 2*t;
                    base2[(size_t)c0*plane]       = leaky(acc[mt][nt][2*half + 0] + sbias[c0]);
                    base2[(size_t)(c0 + 1)*plane] = leaky(acc[mt][nt][2*half + 1] + sbias[c0 + 1]);
                }
            }
        }
    }
}

// ---------------- launch ----------------
static const int SMEM_C1 = 648*64 + 256;              // 41728
static const int SMEM_C2 = 648*128 + 16384 + 256;     // 99584

extern "C" void kernel_launch(void* const* d_in, const int* in_sizes, int n_in,
                              void* d_out, int out_size)
{
    (void)in_sizes; (void)n_in; (void)out_size;
    const float* x       = (const float*)d_in[0];
    const float* s       = (const float*)d_in[1];
    const float* skip_w1 = (const float*)d_in[2];
    const float* skip_b1 = (const float*)d_in[3];
    const float* skip_w2 = (const float*)d_in[4];
    const float* skip_b2 = (const float*)d_in[5];
    const float* skip_w3 = (const float*)d_in[6];
    const float* skip_b3 = (const float*)d_in[7];
    const float* skip_wc = (const float*)d_in[8];
    const float* skip_bc = (const float*)d_in[9];
    const float* c1_w1   = (const float*)d_in[10];
    const float* c1_b1   = (const float*)d_in[11];
    const float* c1_w2   = (const float*)d_in[12];
    const float* c1_b2   = (const float*)d_in[13];
    const float* c1_w3   = (const float*)d_in[14];
    const float* c1_b3   = (const float*)d_in[15];
    const float* c1_wc   = (const float*)d_in[16];
    const float* c1_bc   = (const float*)d_in[17];
    const float* c2_w1   = (const float*)d_in[18];
    const float* c2_b1   = (const float*)d_in[19];
    const float* c2_w2   = (const float*)d_in[20];
    const float* c2_b2   = (const float*)d_in[21];
    const float* c2_w3   = (const float*)d_in[22];
    const float* c2_b3   = (const float*)d_in[23];
    const float* c2_wc   = (const float*)d_in[24];
    const float* c2_bc   = (const float*)d_in[25];

    __half *p_xcl, *p_h, *p_w1, *p_w2, *p_ws;
    cudaGetSymbolAddress((void**)&p_xcl, g_xcl);
    cudaGetSymbolAddress((void**)&p_h,   g_h);
    cudaGetSymbolAddress((void**)&p_w1,  g_wc1);
    cudaGetSymbolAddress((void**)&p_w2,  g_wc2);
    cudaGetSymbolAddress((void**)&p_ws,  g_wsk);

    cudaFuncSetAttribute((const void*)conv_mma<96,94,32,27,false>,
                         cudaFuncAttributeMaxDynamicSharedMemorySize, SMEM_C1);
    cudaFuncSetAttribute((const void*)conv_mma<94,92,64,55,true>,
                         cudaFuncAttributeMaxDynamicSharedMemorySize, SMEM_C2);

    prep_kernel<<<2, 256>>>(s, skip_w1, skip_b1, skip_w2, skip_b2, skip_w3, skip_b3,
                            skip_wc, p_ws, 64, 64, 32, 1);
    prep_kernel<<<2, 256>>>(s, c1_w1, c1_b1, c1_w2, c1_b2, c1_w3, c1_b3,
                            c1_wc, p_w1, 64, 64, 32, 27);
    prep_kernel<<<2, 256>>>(s, c2_w1, c2_b1, c2_w2, c2_b2, c2_w3, c2_b3,
                            c2_wc, p_w2, 128, 128, 64, 27);
    xconvert_kernel<<<dim3(96,96,2), 128>>>(x, p_xcl);

    // c1: xcl -> h (channels-last fp16, bias+leaky applied)
    conv_mma<96,94,32,27,false><<<dim3(6,24,48), 128, SMEM_C1>>>(
        p_xcl, p_w1, nullptr, nullptr, c1_bc, nullptr, (void*)p_h);

    // c2 + fused skip + both biases + final leaky -> NCDHW fp32 out
    conv_mma<94,92,64,55,true><<<dim3(6,23,46), 128, SMEM_C2>>>(
        p_h, p_w2, p_ws, p_xcl, c2_bc, skip_bc, d_out);
}

// round 16
// speedup vs baseline: 1.1093x; 1.1093x over previous
#include <cuda_runtime.h>
#include <cuda_fp16.h>
#include <cstdint>

__device__ __forceinline__ float leaky(float v){ return v > 0.f ? v : 0.01f*v; }
__device__ __forceinline__ uint32_t smem_u32(const void* p){
    uint32_t a; asm("{ .reg .u64 t; cvta.to.shared.u64 t, %1; cvt.u32.u64 %0, t; }" : "=r"(a) : "l"(p));
    return a;
}
__device__ __forceinline__ void cpa16(uint32_t dst, const void* src, uint32_t sz){
    asm volatile("cp.async.cg.shared.global [%0], [%1], 16, %2;"
                 :: "r"(dst), "l"(src), "r"(sz) : "memory");
}
#define CP_COMMIT() asm volatile("cp.async.commit_group;" ::: "memory")
#define CP_WAIT1()  asm volatile("cp.async.wait_group 1;" ::: "memory")
#define CP_WAIT0()  asm volatile("cp.async.wait_group 0;" ::: "memory")

__device__ __forceinline__ void mma16(float* c, const uint32_t* a, uint32_t b0, uint32_t b1){
    asm volatile("mma.sync.aligned.m16n8k16.row.col.f32.f16.f16.f32 "
        "{%0,%1,%2,%3}, {%4,%5,%6,%7}, {%8,%9}, {%0,%1,%2,%3};"
        : "+f"(c[0]), "+f"(c[1]), "+f"(c[2]), "+f"(c[3])
        : "r"(a[0]), "r"(a[1]), "r"(a[2]), "r"(a[3]), "r"(b0), "r"(b1));
}
__device__ __forceinline__ void ldmA(uint32_t* a, uint32_t addr){
    asm volatile("ldmatrix.sync.aligned.m8n8.x4.shared.b16 {%0,%1,%2,%3}, [%4];"
        : "=r"(a[0]), "=r"(a[1]), "=r"(a[2]), "=r"(a[3]) : "r"(addr));
}
__device__ __forceinline__ void stcs_f32(float* p, float v){
    asm volatile("st.global.cs.f32 [%0], %1;" :: "l"(p), "f"(v) : "memory");
}
__device__ __forceinline__ uint32_t h2_bits(float lo, float hi){
    __half2 h = __floats2half2_rn(lo, hi);
    uint32_t u;
    asm("mov.b32 %0, %1;" : "=r"(u) : "r"(*(uint32_t*)&h));
    return u;
}

// ---------------- device scratch ----------------
__device__ __align__(16) __half g_xcl[(size_t)2*96*96*96*32];   // x channels-last fp16
__device__ __align__(16) __half g_h  [(size_t)2*94*94*94*64];   // h channels-last fp16
__device__ __align__(16) __half g_wc1[2*27*2048];               // B fragments per 32-K chunk
__device__ __align__(16) __half g_wc2[2*54*2048];
__device__ __align__(16) __half g_wsk[2*2048];

// ---------------- prep: style MLP + modulate/demod + fp16 B-fragment tiles ----------------
__global__ void prep_kernel(const float* __restrict__ s,
                            const float* __restrict__ w1, const float* __restrict__ b1,
                            const float* __restrict__ w2, const float* __restrict__ b2,
                            const float* __restrict__ w3, const float* __restrict__ b3,
                            const float* __restrict__ wc, __half* __restrict__ gw,
                            int H1, int H2, int IC, int KD)
{
    const int n = blockIdx.x, tid = threadIdx.x;
    __shared__ float sv[64], a1[128], a2[128], mod[64], dem[64];
    if (tid < 64) sv[tid] = s[n*64 + tid];
    __syncthreads();
    if (tid < H1){
        float a = b1[tid];
        for (int k = 0; k < 64; k++) a += sv[k]*w1[tid*64 + k];
        a1[tid] = leaky(a);
    }
    __syncthreads();
    if (tid < H2){
        float a = b2[tid];
        for (int k = 0; k < H1; k++) a += a1[k]*w2[tid*H1 + k];
        a2[tid] = leaky(a);
    }
    __syncthreads();
    if (tid < IC){
        float a = b3[tid];
        for (int k = 0; k < H2; k++) a += a2[k]*w3[tid*H2 + k];
        mod[tid] = a;
    }
    __syncthreads();
    if (tid < 64){
        float ss = 0.f;
        for (int i = 0; i < IC; i++){
            float m = mod[i];
            const float* wp = wc + (tid*IC + i)*KD;
            for (int k = 0; k < KD; k++){ float t = wp[k]*m; ss += t*t; }
        }
        dem[tid] = rsqrtf(ss + 1e-8f);
    }
    __syncthreads();
    const int nsub = IC >> 5;
    const int total = KD * nsub * 2048;
    for (int e = tid; e < total; e += blockDim.x){
        int j    = e & 7;
        int lane = (e >> 3) & 31;
        int nt   = (e >> 8) & 7;
        int c    = e >> 11;
        int g    = lane >> 2, t = lane & 3;
        int oc   = nt*8 + g;
        int kloc = (j >> 2)*16 + 2*t + (j & 1) + 8*((j >> 1) & 1);
        int tap  = c / nsub, ih = c % nsub;
        int ic   = ih*32 + kloc;
        gw[(size_t)n*total + e] = __float2half_rn(wc[(oc*IC + ic)*KD + tap] * mod[ic] * dem[oc]);
    }
}

// ---------------- x -> channels-last fp16 (vectorized) ----------------
// Block: one (z,y) row; read 32 ch x 96 x as float4, write 96 voxels x 32 ch as uint4.
__global__ void xconvert_kernel(const float* __restrict__ x, __half* __restrict__ xcl)
{
    const int y = blockIdx.x, z = blockIdx.y, n = blockIdx.z;
    __shared__ float sm[32*97];
    const float* src = x + (size_t)n*28311552 + (size_t)z*9216 + (size_t)y*96;
    // 32 rows x 24 float4 = 768 float4 reads
    for (int e = threadIdx.x; e < 768; e += 128){
        int ic = e / 24, q = e % 24;
        float4 v = *(const float4*)(src + (size_t)ic*884736 + q*4);
        float* d = sm + ic*97 + q*4;
        d[0] = v.x; d[1] = v.y; d[2] = v.z; d[3] = v.w;
    }
    __syncthreads();
    __half* dst = xcl + (size_t)n*28311552 + ((size_t)z*96 + y)*96*32;
    // 96 voxels x 4 uint4 (8 halfs each)
    for (int e = threadIdx.x; e < 384; e += 128){
        int xx = e >> 2, cg = e & 3;
        const float* sp = sm + (cg*8)*97 + xx;
        uint4 o;
        o.x = h2_bits(sp[0],    sp[97]);
        o.y = h2_bits(sp[2*97], sp[3*97]);
        o.z = h2_bits(sp[4*97], sp[5*97]);
        o.w = h2_bits(sp[6*97], sp[7*97]);
        *(uint4*)(dst + (size_t)xx*32 + cg*8) = o;
    }
}

// ---------------- implicit-GEMM conv: A-resident halo, reg-B, two-phase prologue ----------------
// CTA: 128 threads / 4 warps; tile M=256 voxels (4z x 4y x 16x) x N=64 oc.
// Halo split into group A (hz<=3) and group B (hz>=4 + skip tile); MMAs start
// after group A only. Tap-level addr-gen. Per chunk: ldmA x8, then the 8
// independent B-prefetch LDGs (covering LDSM latency), then the two MMA blocks.
template<int IND, int OUTD, int INCH, int NCH, bool SKIP>
__global__ __launch_bounds__(128, 2)
void conv_mma(const __half* __restrict__ in,
              const __half* __restrict__ wtil,
              const __half* __restrict__ wskip,
              const __half* __restrict__ xclp,
              const float* __restrict__ bias1,
              const float* __restrict__ bias2,
              void* __restrict__ outp)
{
    constexpr int NSUB = INCH >> 5;
    constexpr int ZT   = (OUTD + 3) / 4;
    constexpr int CHB  = INCH * 2;
    constexpr int P    = CHB / 16;
    constexpr int HALO = 648 * CHB;
    constexpr int SKT  = SKIP ? 16384 : 0;
    constexpr int BIAS = HALO + SKT;
    constexpr int TOTA = 432 * P;           // hz 0..3
    constexpr int TOT  = 648 * P;

    extern __shared__ __align__(16) unsigned char smem[];
    const uint32_t sb = smem_u32(smem);
    float* sbias = (float*)(smem + BIAS);

    const int tid  = threadIdx.x;
    const int lane = tid & 31;
    const int g    = lane >> 2;
    const int t    = lane & 3;
    const int strip = (tid >> 5) * 64;

    const int bx = blockIdx.x, by = blockIdx.y;
    const int n  = blockIdx.z / ZT;
    const int zt = blockIdx.z % ZT;
    const int z0 = zt*4, y0 = by*4, x0 = bx*16;

    const __half* inb = in + (size_t)n*IND*IND*IND*INCH;
    const __half* xb  = SKIP ? (xclp + (size_t)n*28311552) : nullptr;
    const __half* wb  = wtil + (size_t)n*(NCH - (SKIP?1:0))*2048;
    const __half* wsb = SKIP ? (wskip + (size_t)n*2048) : nullptr;

    if (tid < 64){
        float b = bias1[tid];
        if constexpr (SKIP) b += bias2[tid];
        sbias[tid] = b;
    }

    // ---- halo group A: hz 0..3 ----
    #pragma unroll 4
    for (int e = tid; e < TOTA; e += 128){
        int vox = e / P, j = e % P;
        int hx = vox % 18, hy = (vox/18) % 6, hz = vox/108;
        bool v = (z0+hz < IND) && (y0+hy < IND) && (x0+hx < IND);
        int key = (INCH == 64) ? (hx & 7) : ((hx >> 1) & 3);
        uint32_t dst = sb + (uint32_t)(vox*CHB + ((j ^ key) << 4));
        const __half* src = inb + (((size_t)(z0+hz)*IND + (y0+hy))*IND + (x0+hx))*INCH + j*8;
        cpa16(dst, src, v ? 16u : 0u);
    }
    CP_COMMIT();
    // ---- halo group B: hz 4..5 (+ skip tile) ----
    #pragma unroll 2
    for (int e = TOTA + tid; e < TOT; e += 128){
        int vox = e / P, j = e % P;
        int hx = vox % 18, hy = (vox/18) % 6, hz = vox/108;
        bool v = (z0+hz < IND) && (y0+hy < IND) && (x0+hx < IND);
        int key = (INCH == 64) ? (hx & 7) : ((hx >> 1) & 3);
        uint32_t dst = sb + (uint32_t)(vox*CHB + ((j ^ key) << 4));
        const __half* src = inb + (((size_t)(z0+hz)*IND + (y0+hy))*IND + (x0+hx))*INCH + j*8;
        cpa16(dst, src, v ? 16u : 0u);
    }
    if constexpr (SKIP){
        #pragma unroll 2
        for (int e = tid; e < 1024; e += 128){
            int vox = e >> 2, j = e & 3;
            int dx = vox & 15, dy = (vox >> 4) & 3, dz = vox >> 6;
            bool v = (z0+2+dz < 96) && (y0+2+dy < 96) && (x0+2+dx < 96);
            int key = (dx >> 1) & 3;
            uint32_t dst = sb + (uint32_t)(HALO + vox*64 + ((j ^ key) << 4));
            const __half* src = xb + (((size_t)(z0+2+dz)*96 + (y0+2+dy))*96 + (x0+2+dx))*32 + j*8;
            cpa16(dst, src, v ? 16u : 0u);
        }
    }
    CP_COMMIT();
    CP_WAIT1();               // group A complete; group B may still fly
    __syncthreads();

    const int r  = ((lane >> 3) & 1)*8 + (lane & 7);
    const int kh = (lane >> 4) & 1;

    float acc[4][8][4];
    #pragma unroll
    for (int mt = 0; mt < 4; mt++)
        #pragma unroll
        for (int nt = 0; nt < 8; nt++)
            #pragma unroll
            for (int q = 0; q < 4; q++) acc[mt][nt][q] = 0.f;

    auto bptr = [&](int kc) -> const uint4* {
        const __half* bs = (SKIP && kc == NCH-1) ? wsb : (wb + (size_t)kc*2048);
        return (const uint4*)bs + lane;
    };

    uint4 bcur[8];
    {
        const uint4* p = bptr(0);
        #pragma unroll
        for (int nt = 0; nt < 8; nt++) bcur[nt] = __ldg(p + nt*32);
    }

    #pragma unroll 1
    for (int tap = 0; tap < 27; tap++){
        if (tap == 9){ CP_WAIT0(); __syncthreads(); }   // group B ready before kz>=1

        const int kz = tap/9, ky = (tap%9)/3, kx = tap%3;
        uint32_t base[4]; int key[4];
        #pragma unroll
        for (int mt = 0; mt < 4; mt++){
            int m = strip + mt*16 + r;
            int hz = (m >> 6) + kz, hy = ((m >> 4) & 3) + ky, hx = (m & 15) + kx;
            int hi = (hz*6 + hy)*18 + hx;
            key[mt]  = (INCH == 64) ? (hx & 7) : ((hx >> 1) & 3);
            base[mt] = sb + (uint32_t)(hi*CHB);
        }

        #pragma unroll
        for (int ih = 0; ih < NSUB; ih++){
            const int kc = tap*NSUB + ih;
            const int slotbase = ih*4;

            // 8 ldmatrix for both k-steps of this chunk
            uint32_t a[2][4][4];
            #pragma unroll
            for (int s = 0; s < 2; s++)
                #pragma unroll
                for (int mt = 0; mt < 4; mt++){
                    int slot = slotbase + 2*s + kh;
                    ldmA(a[s][mt], base[mt] + (uint32_t)((slot ^ key[mt]) << 4));
                }

            // B prefetch for next chunk NOW: 8 independent LDGs fill the
            // LDSM-latency shadow before the first dependent MMA issues.
            uint4 bnxt[8];
            const bool pf = (kc + 1 < NCH);
            if (pf){
                const uint4* p = bptr(kc + 1);
                #pragma unroll
                for (int nt = 0; nt < 8; nt++) bnxt[nt] = __ldg(p + nt*32);
            }

            #pragma unroll
            for (int nt = 0; nt < 8; nt++)
                #pragma unroll
                for (int mt = 0; mt < 4; mt++)
                    mma16(acc[mt][nt], a[0][mt], bcur[nt].x, bcur[nt].y);

            #pragma unroll
            for (int nt = 0; nt < 8; nt++)
                #pragma unroll
                for (int mt = 0; mt < 4; mt++)
                    mma16(acc[mt][nt], a[1][mt], bcur[nt].z, bcur[nt].w);

            if (pf){
                #pragma unroll
                for (int nt = 0; nt < 8; nt++) bcur[nt] = bnxt[nt];
            }
        }
    }

    if constexpr (SKIP){
        // final chunk: 1x1 skip conv on x tile; bcur holds wskip fragments
        uint32_t a[2][4][4];
        #pragma unroll
        for (int mt = 0; mt < 4; mt++){
            int m = strip + mt*16 + r;
            int key2 = ((m & 15) >> 1) & 3;
            uint32_t base2 = sb + (uint32_t)(HALO + m*64);
            #pragma unroll
            for (int s = 0; s < 2; s++){
                int slot = 2*s + kh;
                ldmA(a[s][mt], base2 + (uint32_t)((slot ^ key2) << 4));
            }
        }
        #pragma unroll
        for (int nt = 0; nt < 8; nt++)
            #pragma unroll
            for (int mt = 0; mt < 4; mt++){
                mma16(acc[mt][nt], a[0][mt], bcur[nt].x, bcur[nt].y);
                mma16(acc[mt][nt], a[1][mt], bcur[nt].z, bcur[nt].w);
            }
    }

    // ---------------- epilogue ----------------
    #pragma unroll
    for (int mt = 0; mt < 4; mt++){
        #pragma unroll
        for (int half = 0; half < 2; half++){
            const int row = strip + mt*16 + g + 8*half;
            const int vz = z0 + (row >> 6);
            const int vy = y0 + ((row >> 4) & 3);
            const int vx = x0 + (row & 15);
            if (vz >= OUTD || vy >= OUTD || vx >= OUTD) continue;
            if constexpr (!SKIP){
                __half* dst = (__half*)outp + (((size_t)n*OUTD*OUTD*OUTD)
                            + (((size_t)vz*OUTD + vy)*OUTD + vx))*64;
                #pragma unroll
                for (int nt = 0; nt < 8; nt++){
                    const int c0 = nt*8 + 2*t;
                    float v0 = leaky(acc[mt][nt][2*half + 0] + sbias[c0]);
                    float v1 = leaky(acc[mt][nt][2*half + 1] + sbias[c0 + 1]);
                    *(__half2*)(dst + c0) = __floats2half2_rn(v0, v1);
                }
            } else {
                const size_t plane = (size_t)OUTD*OUTD*OUTD;
                float* base2 = (float*)outp + (size_t)n*64*plane
                             + (((size_t)vz*OUTD + vy)*OUTD + vx);
                #pragma unroll
                for (int nt = 0; nt < 8; nt++){
                    const int c0 = nt*8 + 2*t;
                    stcs_f32(base2 + (size_t)c0*plane,
                             leaky(acc[mt][nt][2*half + 0] + sbias[c0]));
                    stcs_f32(base2 + (size_t)(c0 + 1)*plane,
                             leaky(acc[mt][nt][2*half + 1] + sbias[c0 + 1]));
                }
            }
        }
    }
}

// ---------------- launch ----------------
static const int SMEM_C1 = 648*64 + 256;              // 41728
static const int SMEM_C2 = 648*128 + 16384 + 256;     // 99584

extern "C" void kernel_launch(void* const* d_in, const int* in_sizes, int n_in,
                              void* d_out, int out_size)
{
    (void)in_sizes; (void)n_in; (void)out_size;
    const float* x       = (const float*)d_in[0];
    const float* s       = (const float*)d_in[1];
    const float* skip_w1 = (const float*)d_in[2];
    const float* skip_b1 = (const float*)d_in[3];
    const float* skip_w2 = (const float*)d_in[4];
    const float* skip_b2 = (const float*)d_in[5];
    const float* skip_w3 = (const float*)d_in[6];
    const float* skip_b3 = (const float*)d_in[7];
    const float* skip_wc = (const float*)d_in[8];
    const float* skip_bc = (const float*)d_in[9];
    const float* c1_w1   = (const float*)d_in[10];
    const float* c1_b1   = (const float*)d_in[11];
    const float* c1_w2   = (const float*)d_in[12];
    const float* c1_b2   = (const float*)d_in[13];
    const float* c1_w3   = (const float*)d_in[14];
    const float* c1_b3   = (const float*)d_in[15];
    const float* c1_wc   = (const float*)d_in[16];
    const float* c1_bc   = (const float*)d_in[17];
    const float* c2_w1   = (const float*)d_in[18];
    const float* c2_b1   = (const float*)d_in[19];
    const float* c2_w2   = (const float*)d_in[20];
    const float* c2_b2   = (const float*)d_in[21];
    const float* c2_w3   = (const float*)d_in[22];
    const float* c2_b3   = (const float*)d_in[23];
    const float* c2_wc   = (const float*)d_in[24];
    const float* c2_bc   = (const float*)d_in[25];

    __half *p_xcl, *p_h, *p_w1, *p_w2, *p_ws;
    cudaGetSymbolAddress((void**)&p_xcl, g_xcl);
    cudaGetSymbolAddress((void**)&p_h,   g_h);
    cudaGetSymbolAddress((void**)&p_w1,  g_wc1);
    cudaGetSymbolAddress((void**)&p_w2,  g_wc2);
    cudaGetSymbolAddress((void**)&p_ws,  g_wsk);

    cudaFuncSetAttribute((const void*)conv_mma<96,94,32,27,false>,
                         cudaFuncAttributeMaxDynamicSharedMemorySize, SMEM_C1);
    cudaFuncSetAttribute((const void*)conv_mma<94,92,64,55,true>,
                         cudaFuncAttributeMaxDynamicSharedMemorySize, SMEM_C2);

    prep_kernel<<<2, 256>>>(s, skip_w1, skip_b1, skip_w2, skip_b2, skip_w3, skip_b3,
                            skip_wc, p_ws, 64, 64, 32, 1);
    prep_kernel<<<2, 256>>>(s, c1_w1, c1_b1, c1_w2, c1_b2, c1_w3, c1_b3,
                            c1_wc, p_w1, 64, 64, 32, 27);
    prep_kernel<<<2, 256>>>(s, c2_w1, c2_b1, c2_w2, c2_b2, c2_w3, c2_b3,
                            c2_wc, p_w2, 128, 128, 64, 27);
    xconvert_kernel<<<dim3(96,96,2), 128>>>(x, p_xcl);

    // c1: xcl -> h (channels-last fp16, bias+leaky applied)
    conv_mma<96,94,32,27,false><<<dim3(6,24,48), 128, SMEM_C1>>>(
        p_xcl, p_w1, nullptr, nullptr, c1_bc, nullptr, (void*)p_h);

    // c2 + fused skip + both biases + final leaky -> NCDHW fp32 out
    conv_mma<94,92,64,55,true><<<dim3(6,23,46), 128, SMEM_C2>>>(
        p_h, p_w2, p_ws, p_xcl, c2_bc, skip_bc, d_out);
}